// round 4
// baseline (speedup 1.0000x reference)
#include <cuda_runtime.h>
#include <cuda_bf16.h>

// ChamferDistance: B=4, C=3, N=M=8192, fp32.
// Shared dot products: t(n,m) = x.y - hx - hy = -0.5*||x-y||^2 <= 0.
// min_m dist(n,.) = -2*max_m t;  min_n dist(.,m) = -2*max_n t  -> ONE pass, dual reduction.
// m-side max: persistent registers (thread owns 8 m's).
// n-side: fmax tournament + __reduce_min_sync on raw bits (max of non-positive floats
//         == min of uint bit patterns). Cross-block merge: atomicMin on raw bits.

#define NPTS    8192
#define NBATCH  4
#define THREADS 256
#define QM      8                      // target points per thread (persistent)
#define MTILE   (THREADS * QM)         // 2048 m per block
#define NMT     (NPTS / MTILE)         // 4 m-tiles
#define NRANGE  64                     // n's per block
#define NNS     (NPTS / NRANGE)        // 128 n-splits
#define NBLOCKS (NBATCH * NMT * NNS)   // 2048
#define NKEYS   (2 * NBATCH * NPTS)    // 65536: [0..32767] pred-side (n), rest targ-side (m)
#define NEG_INF (-3.402823466e38f)

__device__ unsigned g_key[NKEYS];      // raw float bits of running max-t (umin order)

typedef unsigned long long u64;

__device__ __forceinline__ u64 fma2(u64 a, u64 b, u64 c) {
    u64 d;
    asm("fma.rn.f32x2 %0, %1, %2, %3;" : "=l"(d) : "l"(a), "l"(b), "l"(c));
    return d;
}
__device__ __forceinline__ u64 pack_ab(float lo, float hi) {
    u64 d;
    asm("mov.b64 %0, {%1, %2};" : "=l"(d) : "f"(lo), "f"(hi));
    return d;
}
__device__ __forceinline__ void unpack2(u64 v, float& lo, float& hi) {
    asm("mov.b64 {%0, %1}, %2;" : "=f"(lo), "=f"(hi) : "l"(v));
}
__device__ __forceinline__ void lds_v2u64(unsigned addr, u64& a, u64& b) {
    asm volatile("ld.shared.v2.u64 {%0, %1}, [%2];" : "=l"(a), "=l"(b) : "r"(addr));
}

__global__ void chamfer_nop_kernel() {}

__global__ void chamfer_init_kernel() {
    int i = blockIdx.x * blockDim.x + threadIdx.x;
    g_key[i] = 0xFFFFFFFFu;   // umin identity (worse than any real t's bits)
}

__global__ __launch_bounds__(THREADS, 3)
void chamfer_main_kernel(const float* __restrict__ pred,
                         const float* __restrict__ targ) {
    const int u  = blockIdx.x;
    const int ns = u % NNS;
    const int mt = (u / NNS) % NMT;
    const int b  = u / (NNS * NMT);

    const float* __restrict__ X = pred + (size_t)b * 3 * NPTS;   // n-side (pred)
    const float* __restrict__ Y = targ + (size_t)b * 3 * NPTS;   // m-side (targ)

    __shared__ float4   s_n[NRANGE * 2];    // per n: {x0,x0,x1,x1}, {x2,x2,nhx,nhx}
    __shared__ unsigned s_nf[NRANGE * 8];   // per n per warp: warp-level n-partial (raw bits)

    const int tid  = threadIdx.x;
    const int lane = tid & 31;
    const int wid  = tid >> 5;

    // ---- persistent m-data: QM=8 targets per thread, packed pairs ----
    const int m0 = mt * MTILE + tid * QM;
    float y0[QM], y1[QM], y2[QM], nhy[QM];
    {
        const float4* Y0 = (const float4*)(Y + m0);
        const float4* Y1 = (const float4*)(Y + NPTS + m0);
        const float4* Y2 = (const float4*)(Y + 2 * NPTS + m0);
        float4 a, c;
        a = Y0[0]; c = Y0[1];
        y0[0]=a.x; y0[1]=a.y; y0[2]=a.z; y0[3]=a.w; y0[4]=c.x; y0[5]=c.y; y0[6]=c.z; y0[7]=c.w;
        a = Y1[0]; c = Y1[1];
        y1[0]=a.x; y1[1]=a.y; y1[2]=a.z; y1[3]=a.w; y1[4]=c.x; y1[5]=c.y; y1[6]=c.z; y1[7]=c.w;
        a = Y2[0]; c = Y2[1];
        y2[0]=a.x; y2[1]=a.y; y2[2]=a.z; y2[3]=a.w; y2[4]=c.x; y2[5]=c.y; y2[6]=c.z; y2[7]=c.w;
    }
    #pragma unroll
    for (int j = 0; j < QM; j++)
        nhy[j] = -0.5f * (y0[j]*y0[j] + y1[j]*y1[j] + y2[j]*y2[j]);

    u64 Y0p[QM/2], Y1p[QM/2], Y2p[QM/2], NHp[QM/2];
    #pragma unroll
    for (int k = 0; k < QM/2; k++) {
        Y0p[k] = pack_ab(y0[2*k], y0[2*k+1]);
        Y1p[k] = pack_ab(y1[2*k], y1[2*k+1]);
        Y2p[k] = pack_ab(y2[2*k], y2[2*k+1]);
        NHp[k] = pack_ab(nhy[2*k], nhy[2*k+1]);
    }
    const u64 ONESp = pack_ab(1.0f, 1.0f);

    float my[QM];
    #pragma unroll
    for (int j = 0; j < QM; j++) my[j] = NEG_INF;

    // ---- stage n-data: duplicated pairs for broadcast LDS.128 ----
    if (tid < NRANGE) {
        int n = ns * NRANGE + tid;
        float x0 = X[n];
        float x1 = X[NPTS + n];
        float x2 = X[2 * NPTS + n];
        float nhx = -0.5f * (x0*x0 + x1*x1 + x2*x2);
        s_n[tid * 2 + 0] = make_float4(x0, x0, x1, x1);
        s_n[tid * 2 + 1] = make_float4(x2, x2, nhx, nhx);
    }
    __syncthreads();

    const unsigned sbase = (unsigned)__cvta_generic_to_shared(s_n);

    // ---- main loop over n: 8 (n,m) pairs per thread per n, both directions ----
    #pragma unroll 4
    for (int nl = 0; nl < NRANGE; nl++) {
        u64 xA, xB, xC, xH;
        lds_v2u64(sbase + nl * 32, xA, xB);        // {x0,x0},{x1,x1}
        lds_v2u64(sbase + nl * 32 + 16, xC, xH);   // {x2,x2},{nhx,nhx}

        u64 t0 = fma2(xH, ONESp, NHp[0]);          // nhx + nhy
        u64 t1 = fma2(xH, ONESp, NHp[1]);
        u64 t2 = fma2(xH, ONESp, NHp[2]);
        u64 t3 = fma2(xH, ONESp, NHp[3]);
        t0 = fma2(xA, Y0p[0], t0);
        t1 = fma2(xA, Y0p[1], t1);
        t2 = fma2(xA, Y0p[2], t2);
        t3 = fma2(xA, Y0p[3], t3);
        t0 = fma2(xB, Y1p[0], t0);
        t1 = fma2(xB, Y1p[1], t1);
        t2 = fma2(xB, Y1p[2], t2);
        t3 = fma2(xB, Y1p[3], t3);
        t0 = fma2(xC, Y2p[0], t0);
        t1 = fma2(xC, Y2p[1], t1);
        t2 = fma2(xC, Y2p[2], t2);
        t3 = fma2(xC, Y2p[3], t3);

        float v0, v1, v2, v3, v4, v5, v6, v7;
        unpack2(t0, v0, v1);
        unpack2(t1, v2, v3);
        unpack2(t2, v4, v5);
        unpack2(t3, v6, v7);

        // m-side running maxes (registers, persistent)
        my[0] = fmaxf(my[0], v0);
        my[1] = fmaxf(my[1], v1);
        my[2] = fmaxf(my[2], v2);
        my[3] = fmaxf(my[3], v3);
        my[4] = fmaxf(my[4], v4);
        my[5] = fmaxf(my[5], v5);
        my[6] = fmaxf(my[6], v6);
        my[7] = fmaxf(my[7], v7);

        // n-side: thread tournament, then warp reduce on raw bits
        // (all t <= 0, so float-max == uint-min on bit patterns)
        float p0 = fmaxf(v0, v1), p1 = fmaxf(v2, v3);
        float p2 = fmaxf(v4, v5), p3 = fmaxf(v6, v7);
        float nm = fmaxf(fmaxf(p0, p1), fmaxf(p2, p3));
        unsigned wm = __reduce_min_sync(0xffffffffu, __float_as_uint(nm));
        if (lane == 0) s_nf[nl * 8 + wid] = wm;
    }
    __syncthreads();

    // ---- m-side epilogue: global key-min (complete over this block's n-range) ----
    const int mkey0 = (NBATCH + b) * NPTS + m0;
    #pragma unroll
    for (int j = 0; j < QM; j++)
        atomicMin(&g_key[mkey0 + j], __float_as_uint(my[j]));

    // ---- n-side epilogue: fold 8 warp-partials per n, then global key-min ----
    if (tid < NRANGE) {
        const unsigned* f = &s_nf[tid * 8];
        unsigned s = min(min(min(f[0], f[1]), min(f[2], f[3])),
                         min(min(f[4], f[5]), min(f[6], f[7])));
        atomicMin(&g_key[b * NPTS + ns * NRANGE + tid], s);
    }
}

__global__ __launch_bounds__(1024)
void chamfer_reduce_kernel(float* __restrict__ out) {
    __shared__ float wsum[32];
    float s = 0.0f;
    for (int i = threadIdx.x; i < NKEYS; i += 1024)
        s += __uint_as_float(g_key[i]);
    #pragma unroll
    for (int off = 16; off > 0; off >>= 1)
        s += __shfl_xor_sync(0xffffffffu, s, off);
    if ((threadIdx.x & 31) == 0) wsum[threadIdx.x >> 5] = s;
    __syncthreads();
    if (threadIdx.x == 0) {
        float t = 0.0f;
        #pragma unroll
        for (int i = 0; i < 32; i++) t += wsum[i];
        // each direction's mean divides by B*NPTS; min dist = -2 * max t
        out[0] = t * (-2.0f / (float)(NBATCH * NPTS));
    }
}

extern "C" void kernel_launch(void* const* d_in, const int* in_sizes, int n_in,
                              void* d_out, int out_size) {
    const float* pred = (const float*)d_in[0];
    const float* targ = (const float*)d_in[1];
    float* out = (float*)d_out;

    chamfer_init_kernel<<<NKEYS / 1024, 1024>>>();
    // padding so ncu (-s 5 -c 1) profiles the MAIN kernel (launch index 5)
    chamfer_nop_kernel<<<1, 1>>>();
    chamfer_nop_kernel<<<1, 1>>>();
    chamfer_nop_kernel<<<1, 1>>>();
    chamfer_nop_kernel<<<1, 1>>>();
    chamfer_main_kernel<<<NBLOCKS, THREADS>>>(pred, targ);
    chamfer_reduce_kernel<<<1, 1024>>>(out);
}

// round 5
// speedup vs baseline: 1.0379x; 1.0379x over previous
#include <cuda_runtime.h>
#include <cuda_bf16.h>

// ChamferDistance: B=4, C=3, N=M=8192, fp32.
// Shared dot products: t(n,m) = x.y - hx - hy = -0.5*||x-y||^2 <= 0.
// min_m dist(n,.) = -2*max_m t;  min_n dist(.,m) = -2*max_n t  -> ONE pass, dual reduction.
// m-side max: persistent registers (thread owns 8 m's).
// n-side: fmax tournament + __reduce_min_sync on raw bits (max of non-positive floats
//         == min of uint bit patterns). Cross-block merge: atomicMin on raw bits.
// R5 fixes vs R4: no launch_bounds min-blocks (spills!), unroll 2, nops removed.

#define NPTS    8192
#define NBATCH  4
#define THREADS 256
#define QM      8                      // target points per thread (persistent)
#define MTILE   (THREADS * QM)         // 2048 m per block
#define NMT     (NPTS / MTILE)         // 4 m-tiles
#define NRANGE  64                     // n's per block
#define NNS     (NPTS / NRANGE)        // 128 n-splits
#define NBLOCKS (NBATCH * NMT * NNS)   // 2048
#define NKEYS   (2 * NBATCH * NPTS)    // 65536
#define NEG_INF (-3.402823466e38f)

__device__ unsigned g_key[NKEYS];      // raw float bits of running max-t (umin order)

typedef unsigned long long u64;

__device__ __forceinline__ u64 fma2(u64 a, u64 b, u64 c) {
    u64 d;
    asm("fma.rn.f32x2 %0, %1, %2, %3;" : "=l"(d) : "l"(a), "l"(b), "l"(c));
    return d;
}
__device__ __forceinline__ u64 pack_ab(float lo, float hi) {
    u64 d;
    asm("mov.b64 %0, {%1, %2};" : "=l"(d) : "f"(lo), "f"(hi));
    return d;
}
__device__ __forceinline__ void unpack2(u64 v, float& lo, float& hi) {
    asm("mov.b64 {%0, %1}, %2;" : "=f"(lo), "=f"(hi) : "l"(v));
}
__device__ __forceinline__ void lds_v2u64(unsigned addr, u64& a, u64& b) {
    asm volatile("ld.shared.v2.u64 {%0, %1}, [%2];" : "=l"(a), "=l"(b) : "r"(addr));
}

__global__ void chamfer_init_kernel() {
    int i = blockIdx.x * blockDim.x + threadIdx.x;
    g_key[i] = 0xFFFFFFFFu;   // umin identity
}

__global__ __launch_bounds__(THREADS)
void chamfer_main_kernel(const float* __restrict__ pred,
                         const float* __restrict__ targ) {
    const int u  = blockIdx.x;
    const int ns = u % NNS;
    const int mt = (u / NNS) % NMT;
    const int b  = u / (NNS * NMT);

    const float* __restrict__ X = pred + (size_t)b * 3 * NPTS;   // n-side (pred)
    const float* __restrict__ Y = targ + (size_t)b * 3 * NPTS;   // m-side (targ)

    __shared__ float4   s_n[NRANGE * 2];    // per n: {x0,x0,x1,x1}, {x2,x2,nhx,nhx}
    __shared__ unsigned s_nf[NRANGE * 8];   // per n per warp: warp-level n-partial (raw bits)

    const int tid  = threadIdx.x;
    const int lane = tid & 31;
    const int wid  = tid >> 5;

    // ---- persistent m-data: QM=8 targets per thread, packed pairs ----
    const int m0 = mt * MTILE + tid * QM;
    float y0[QM], y1[QM], y2[QM], nhy[QM];
    {
        const float4* Y0 = (const float4*)(Y + m0);
        const float4* Y1 = (const float4*)(Y + NPTS + m0);
        const float4* Y2 = (const float4*)(Y + 2 * NPTS + m0);
        float4 a, c;
        a = Y0[0]; c = Y0[1];
        y0[0]=a.x; y0[1]=a.y; y0[2]=a.z; y0[3]=a.w; y0[4]=c.x; y0[5]=c.y; y0[6]=c.z; y0[7]=c.w;
        a = Y1[0]; c = Y1[1];
        y1[0]=a.x; y1[1]=a.y; y1[2]=a.z; y1[3]=a.w; y1[4]=c.x; y1[5]=c.y; y1[6]=c.z; y1[7]=c.w;
        a = Y2[0]; c = Y2[1];
        y2[0]=a.x; y2[1]=a.y; y2[2]=a.z; y2[3]=a.w; y2[4]=c.x; y2[5]=c.y; y2[6]=c.z; y2[7]=c.w;
    }
    #pragma unroll
    for (int j = 0; j < QM; j++)
        nhy[j] = -0.5f * (y0[j]*y0[j] + y1[j]*y1[j] + y2[j]*y2[j]);

    u64 Y0p[QM/2], Y1p[QM/2], Y2p[QM/2], NHp[QM/2];
    #pragma unroll
    for (int k = 0; k < QM/2; k++) {
        Y0p[k] = pack_ab(y0[2*k], y0[2*k+1]);
        Y1p[k] = pack_ab(y1[2*k], y1[2*k+1]);
        Y2p[k] = pack_ab(y2[2*k], y2[2*k+1]);
        NHp[k] = pack_ab(nhy[2*k], nhy[2*k+1]);
    }
    const u64 ONESp = pack_ab(1.0f, 1.0f);

    float my[QM];
    #pragma unroll
    for (int j = 0; j < QM; j++) my[j] = NEG_INF;

    // ---- stage n-data: duplicated pairs for broadcast LDS.128 ----
    if (tid < NRANGE) {
        int n = ns * NRANGE + tid;
        float x0 = X[n];
        float x1 = X[NPTS + n];
        float x2 = X[2 * NPTS + n];
        float nhx = -0.5f * (x0*x0 + x1*x1 + x2*x2);
        s_n[tid * 2 + 0] = make_float4(x0, x0, x1, x1);
        s_n[tid * 2 + 1] = make_float4(x2, x2, nhx, nhx);
    }
    __syncthreads();

    const unsigned sbase = (unsigned)__cvta_generic_to_shared(s_n);

    // ---- main loop over n: 8 (n,m) dual-pairs per thread per n ----
    #pragma unroll 2
    for (int nl = 0; nl < NRANGE; nl++) {
        u64 xA, xB, xC, xH;
        lds_v2u64(sbase + nl * 32, xA, xB);        // {x0,x0},{x1,x1}
        lds_v2u64(sbase + nl * 32 + 16, xC, xH);   // {x2,x2},{nhx,nhx}

        u64 t0 = fma2(xH, ONESp, NHp[0]);          // nhx + nhy
        u64 t1 = fma2(xH, ONESp, NHp[1]);
        u64 t2 = fma2(xH, ONESp, NHp[2]);
        u64 t3 = fma2(xH, ONESp, NHp[3]);
        t0 = fma2(xA, Y0p[0], t0);
        t1 = fma2(xA, Y0p[1], t1);
        t2 = fma2(xA, Y0p[2], t2);
        t3 = fma2(xA, Y0p[3], t3);
        t0 = fma2(xB, Y1p[0], t0);
        t1 = fma2(xB, Y1p[1], t1);
        t2 = fma2(xB, Y1p[2], t2);
        t3 = fma2(xB, Y1p[3], t3);
        t0 = fma2(xC, Y2p[0], t0);
        t1 = fma2(xC, Y2p[1], t1);
        t2 = fma2(xC, Y2p[2], t2);
        t3 = fma2(xC, Y2p[3], t3);

        float v0, v1, v2, v3, v4, v5, v6, v7;
        unpack2(t0, v0, v1);
        unpack2(t1, v2, v3);
        unpack2(t2, v4, v5);
        unpack2(t3, v6, v7);

        // m-side running maxes (registers, persistent)
        my[0] = fmaxf(my[0], v0);
        my[1] = fmaxf(my[1], v1);
        my[2] = fmaxf(my[2], v2);
        my[3] = fmaxf(my[3], v3);
        my[4] = fmaxf(my[4], v4);
        my[5] = fmaxf(my[5], v5);
        my[6] = fmaxf(my[6], v6);
        my[7] = fmaxf(my[7], v7);

        // n-side: thread tournament, then warp reduce on raw bits
        float p0 = fmaxf(v0, v1), p1 = fmaxf(v2, v3);
        float p2 = fmaxf(v4, v5), p3 = fmaxf(v6, v7);
        float nm = fmaxf(fmaxf(p0, p1), fmaxf(p2, p3));
        unsigned wm = __reduce_min_sync(0xffffffffu, __float_as_uint(nm));
        if (lane == 0) s_nf[nl * 8 + wid] = wm;
    }
    __syncthreads();

    // ---- m-side epilogue: global key-min (complete over this block's n-range) ----
    const int mkey0 = (NBATCH + b) * NPTS + m0;
    #pragma unroll
    for (int j = 0; j < QM; j++)
        atomicMin(&g_key[mkey0 + j], __float_as_uint(my[j]));

    // ---- n-side epilogue: fold 8 warp-partials per n, then global key-min ----
    if (tid < NRANGE) {
        const unsigned* f = &s_nf[tid * 8];
        unsigned s = min(min(min(f[0], f[1]), min(f[2], f[3])),
                         min(min(f[4], f[5]), min(f[6], f[7])));
        atomicMin(&g_key[b * NPTS + ns * NRANGE + tid], s);
    }
}

__global__ __launch_bounds__(1024)
void chamfer_reduce_kernel(float* __restrict__ out) {
    __shared__ float wsum[32];
    float s = 0.0f;
    for (int i = threadIdx.x; i < NKEYS; i += 1024)
        s += __uint_as_float(g_key[i]);
    #pragma unroll
    for (int off = 16; off > 0; off >>= 1)
        s += __shfl_xor_sync(0xffffffffu, s, off);
    if ((threadIdx.x & 31) == 0) wsum[threadIdx.x >> 5] = s;
    __syncthreads();
    if (threadIdx.x == 0) {
        float t = 0.0f;
        #pragma unroll
        for (int i = 0; i < 32; i++) t += wsum[i];
        out[0] = t * (-2.0f / (float)(NBATCH * NPTS));
    }
}

extern "C" void kernel_launch(void* const* d_in, const int* in_sizes, int n_in,
                              void* d_out, int out_size) {
    const float* pred = (const float*)d_in[0];
    const float* targ = (const float*)d_in[1];
    float* out = (float*)d_out;

    chamfer_init_kernel<<<NKEYS / 1024, 1024>>>();
    chamfer_main_kernel<<<NBLOCKS, THREADS>>>(pred, targ);
    chamfer_reduce_kernel<<<1, 1024>>>(out);
}

// round 6
// speedup vs baseline: 1.1615x; 1.1191x over previous
#include <cuda_runtime.h>
#include <cuda_bf16.h>

// ChamferDistance: B=4, C=3, N=M=8192, fp32 -> scalar.
// Single-direction packed engine (validated R2 core), tuned:
//   t = x.y - 0.5||y||^2 per (query,target); per-query max(t); min dist = 2hx - 2max.
//   Accumulate t_full = max(t) - hx <= 0 -> raw-bit atomicMin merge (umin == fmax for t<=0).
// QPT=8 queries/thread, 4 targets/iter via broadcast LDS.128 from SoA smem.
// Final sum fused into main kernel via last-block pattern (2 launches total).

#define NPTS    8192
#define NBATCH  4
#define THREADS 256
#define QPT     8
#define QTILE   (THREADS * QPT)          // 2048 queries per block
#define NQT     (NPTS / QTILE)           // 4
#define TCHUNK  512                      // targets per block
#define NTC     (NPTS / TCHUNK)          // 16
#define NBLOCKS (2 * NBATCH * NQT * NTC) // 512
#define NKEYS   (2 * NBATCH * NPTS)      // 65536
#define NEG_INF (-3.402823466e38f)

__device__ unsigned g_key[NKEYS];   // raw bits of t_full (<=0), merged via umin
__device__ unsigned g_count;

typedef unsigned long long u64;

__device__ __forceinline__ u64 fma2(u64 a, u64 b, u64 c) {
    u64 d;
    asm("fma.rn.f32x2 %0, %1, %2, %3;" : "=l"(d) : "l"(a), "l"(b), "l"(c));
    return d;
}
__device__ __forceinline__ u64 pack2(float x) {
    u64 d;
    asm("mov.b64 %0, {%1, %1};" : "=l"(d) : "f"(x));
    return d;
}
__device__ __forceinline__ void unpack2(u64 v, float& lo, float& hi) {
    asm("mov.b64 {%0, %1}, %2;" : "=f"(lo), "=f"(hi) : "l"(v));
}
__device__ __forceinline__ void lds_v2u64(unsigned addr, u64& a, u64& b) {
    asm volatile("ld.shared.v2.u64 {%0, %1}, [%2];" : "=l"(a), "=l"(b) : "r"(addr));
}

__global__ void chamfer_init_kernel() {
    int i = blockIdx.x * blockDim.x + threadIdx.x;
    g_key[i] = 0xFFFFFFFFu;   // umin identity
    if (i == 0) g_count = 0u;
}

__global__ __launch_bounds__(THREADS)
void chamfer_main_kernel(const float* __restrict__ pred,
                         const float* __restrict__ targ,
                         float* __restrict__ out) {
    const int u   = blockIdx.x;
    const int tc  = u & (NTC - 1);
    const int qt  = (u >> 4) & (NQT - 1);
    const int b   = (u >> 6) & (NBATCH - 1);
    const int dir = u >> 8;

    const float* __restrict__ X = (dir ? targ : pred) + (size_t)b * 3 * NPTS;  // queries
    const float* __restrict__ Y = (dir ? pred : targ) + (size_t)b * 3 * NPTS;  // targets

    __shared__ float s_y0[TCHUNK], s_y1[TCHUNK], s_y2[TCHUNK], s_nh[TCHUNK];
    __shared__ float wsum[THREADS / 32];
    __shared__ unsigned s_flag;

    const int tid = threadIdx.x;

    // ---- stage target chunk SoA: y0, y1, y2, nh = -0.5*||y||^2 ----
    const int tbase = tc * TCHUNK;
    #pragma unroll
    for (int i = tid; i < TCHUNK; i += THREADS) {
        float y0 = Y[tbase + i];
        float y1 = Y[NPTS + tbase + i];
        float y2 = Y[2 * NPTS + tbase + i];
        s_y0[i] = y0;
        s_y1[i] = y1;
        s_y2[i] = y2;
        s_nh[i] = -0.5f * (y0 * y0 + y1 * y1 + y2 * y2);
    }

    // ---- QPT queries per thread: packed broadcast registers ----
    const int qbase = qt * QTILE;
    u64 xp0[QPT], xp1[QPT], xp2[QPT];
    float hx[QPT];
    #pragma unroll
    for (int q = 0; q < QPT; q++) {
        int n = qbase + q * THREADS + tid;
        float x0 = X[n];
        float x1 = X[NPTS + n];
        float x2 = X[2 * NPTS + n];
        xp0[q] = pack2(x0);
        xp1[q] = pack2(x1);
        xp2[q] = pack2(x2);
        hx[q] = 0.5f * (x0 * x0 + x1 * x1 + x2 * x2);
    }
    __syncthreads();

    const unsigned a0 = (unsigned)__cvta_generic_to_shared(s_y0);
    const unsigned a1 = (unsigned)__cvta_generic_to_shared(s_y1);
    const unsigned a2 = (unsigned)__cvta_generic_to_shared(s_y2);
    const unsigned ah = (unsigned)__cvta_generic_to_shared(s_nh);

    float m0[QPT], m1[QPT];
    #pragma unroll
    for (int q = 0; q < QPT; q++) { m0[q] = NEG_INF; m1[q] = NEG_INF; }

    // ---- main loop: 4 targets/iter (broadcast), 8 queries/thread = 32 pairs ----
    #pragma unroll 2
    for (int j = 0; j < TCHUNK / 4; j++) {
        u64 A0, A1, B0, B1, C0, C1, H0, H1;
        const unsigned off = j * 16;
        lds_v2u64(a0 + off, A0, A1);   // y0[4j..4j+3] as two packed pairs
        lds_v2u64(a1 + off, B0, B1);
        lds_v2u64(a2 + off, C0, C1);
        lds_v2u64(ah + off, H0, H1);

        #pragma unroll
        for (int q = 0; q < QPT; q++) {
            u64 t0 = fma2(xp2[q], C0, H0);
            u64 t1 = fma2(xp2[q], C1, H1);
            t0 = fma2(xp1[q], B0, t0);
            t1 = fma2(xp1[q], B1, t1);
            t0 = fma2(xp0[q], A0, t0);
            t1 = fma2(xp0[q], A1, t1);
            float l0, h0, l1, h1;
            unpack2(t0, l0, h0);
            unpack2(t1, l1, h1);
            m0[q] = fmaxf(m0[q], l0);
            m1[q] = fmaxf(m1[q], h0);
            m0[q] = fmaxf(m0[q], l1);
            m1[q] = fmaxf(m1[q], h1);
        }
    }

    // ---- epilogue: t_full = max - hx <= 0, merge via raw-bit umin ----
    const int key0 = (dir * NBATCH + b) * NPTS + qbase + tid;
    #pragma unroll
    for (int q = 0; q < QPT; q++) {
        float tf = fmaxf(m0[q], m1[q]) - hx[q];
        atomicMin(&g_key[key0 + q * THREADS], __float_as_uint(tf));
    }

    // ---- last block performs the final sum (fused reduce) ----
    __threadfence();
    if (tid == 0)
        s_flag = (atomicAdd(&g_count, 1u) == (unsigned)(NBLOCKS - 1)) ? 1u : 0u;
    __syncthreads();
    if (s_flag) {
        const uint4* kp = (const uint4*)g_key;
        float sa = 0.0f, sb = 0.0f, sc = 0.0f, sd = 0.0f;
        for (int i = tid; i < NKEYS / 4; i += THREADS) {
            uint4 v = __ldcg(&kp[i]);
            sa += __uint_as_float(v.x);
            sb += __uint_as_float(v.y);
            sc += __uint_as_float(v.z);
            sd += __uint_as_float(v.w);
        }
        float s = (sa + sb) + (sc + sd);
        #pragma unroll
        for (int off = 16; off > 0; off >>= 1)
            s += __shfl_xor_sync(0xffffffffu, s, off);
        if ((tid & 31) == 0) wsum[tid >> 5] = s;
        __syncthreads();
        if (tid == 0) {
            float t = 0.0f;
            #pragma unroll
            for (int i = 0; i < THREADS / 32; i++) t += wsum[i];
            // min dist per query = -2 * t_full; two means each over B*NPTS
            out[0] = t * (-2.0f / (float)(NBATCH * NPTS));
        }
    }
}

extern "C" void kernel_launch(void* const* d_in, const int* in_sizes, int n_in,
                              void* d_out, int out_size) {
    const float* pred = (const float*)d_in[0];
    const float* targ = (const float*)d_in[1];
    float* out = (float*)d_out;

    chamfer_init_kernel<<<NKEYS / 1024, 1024>>>();
    chamfer_main_kernel<<<NBLOCKS, THREADS>>>(pred, targ, out);
}

// round 7
// speedup vs baseline: 1.2743x; 1.0971x over previous
#include <cuda_runtime.h>
#include <cuda_bf16.h>

// ChamferDistance: B=4, C=3, N=M=8192, fp32 -> scalar.
// Single-direction packed engine:
//   t = x.y - 0.5||y||^2 per (query,target); per-query max(t); min dist = 2hx - 2max.
//   t_full = max(t) - hx <= 0 -> raw-bit atomicMin merge (umin == fmax for t<=0).
// QPT=8 queries/thread (packed {x,x} broadcast regs), 4 targets/iter via LDS.128 SoA.
// R7: TCHUNK 512 -> 128 (NBLOCKS 512 -> 2048) to kill wave quantization
//     (3 CTAs/SM x 148 = 444 resident; 512 blocks meant a 68-block second wave).

#define NPTS    8192
#define NBATCH  4
#define THREADS 256
#define QPT     8
#define QTILE   (THREADS * QPT)          // 2048 queries per block
#define NQT     (NPTS / QTILE)           // 4
#define TCHUNK  128                      // targets per block
#define NTC     (NPTS / TCHUNK)          // 64
#define NBLOCKS (2 * NBATCH * NQT * NTC) // 2048
#define NKEYS   (2 * NBATCH * NPTS)      // 65536
#define NEG_INF (-3.402823466e38f)

__device__ unsigned g_key[NKEYS];   // raw bits of t_full (<=0), merged via umin
__device__ unsigned g_count;

typedef unsigned long long u64;

__device__ __forceinline__ u64 fma2(u64 a, u64 b, u64 c) {
    u64 d;
    asm("fma.rn.f32x2 %0, %1, %2, %3;" : "=l"(d) : "l"(a), "l"(b), "l"(c));
    return d;
}
__device__ __forceinline__ u64 pack2(float x) {
    u64 d;
    asm("mov.b64 %0, {%1, %1};" : "=l"(d) : "f"(x));
    return d;
}
__device__ __forceinline__ void unpack2(u64 v, float& lo, float& hi) {
    asm("mov.b64 {%0, %1}, %2;" : "=f"(lo), "=f"(hi) : "l"(v));
}
__device__ __forceinline__ void lds_v2u64(unsigned addr, u64& a, u64& b) {
    asm volatile("ld.shared.v2.u64 {%0, %1}, [%2];" : "=l"(a), "=l"(b) : "r"(addr));
}

__global__ void chamfer_init_kernel() {
    int i = blockIdx.x * blockDim.x + threadIdx.x;
    g_key[i] = 0xFFFFFFFFu;   // umin identity
    if (i == 0) g_count = 0u;
}

__global__ __launch_bounds__(THREADS)
void chamfer_main_kernel(const float* __restrict__ pred,
                         const float* __restrict__ targ,
                         float* __restrict__ out) {
    const int u   = blockIdx.x;
    const int tc  = u & (NTC - 1);
    const int qt  = (u >> 6) & (NQT - 1);
    const int b   = (u >> 8) & (NBATCH - 1);
    const int dir = u >> 10;

    const float* __restrict__ X = (dir ? targ : pred) + (size_t)b * 3 * NPTS;  // queries
    const float* __restrict__ Y = (dir ? pred : targ) + (size_t)b * 3 * NPTS;  // targets

    __shared__ float s_y0[TCHUNK], s_y1[TCHUNK], s_y2[TCHUNK], s_nh[TCHUNK];
    __shared__ float wsum[THREADS / 32];
    __shared__ unsigned s_flag;

    const int tid = threadIdx.x;

    // ---- stage target chunk SoA: y0, y1, y2, nh = -0.5*||y||^2 ----
    const int tbase = tc * TCHUNK;
    if (tid < TCHUNK) {
        float y0 = Y[tbase + tid];
        float y1 = Y[NPTS + tbase + tid];
        float y2 = Y[2 * NPTS + tbase + tid];
        s_y0[tid] = y0;
        s_y1[tid] = y1;
        s_y2[tid] = y2;
        s_nh[tid] = -0.5f * (y0 * y0 + y1 * y1 + y2 * y2);
    }

    // ---- QPT queries per thread: packed broadcast registers ----
    const int qbase = qt * QTILE;
    u64 xp0[QPT], xp1[QPT], xp2[QPT];
    float hx[QPT];
    #pragma unroll
    for (int q = 0; q < QPT; q++) {
        int n = qbase + q * THREADS + tid;
        float x0 = X[n];
        float x1 = X[NPTS + n];
        float x2 = X[2 * NPTS + n];
        xp0[q] = pack2(x0);
        xp1[q] = pack2(x1);
        xp2[q] = pack2(x2);
        hx[q] = 0.5f * (x0 * x0 + x1 * x1 + x2 * x2);
    }
    __syncthreads();

    const unsigned a0 = (unsigned)__cvta_generic_to_shared(s_y0);
    const unsigned a1 = (unsigned)__cvta_generic_to_shared(s_y1);
    const unsigned a2 = (unsigned)__cvta_generic_to_shared(s_y2);
    const unsigned ah = (unsigned)__cvta_generic_to_shared(s_nh);

    float m0[QPT], m1[QPT];
    #pragma unroll
    for (int q = 0; q < QPT; q++) { m0[q] = NEG_INF; m1[q] = NEG_INF; }

    // ---- main loop: 4 targets/iter (broadcast), 8 queries/thread = 32 pairs ----
    #pragma unroll 2
    for (int j = 0; j < TCHUNK / 4; j++) {
        u64 A0, A1, B0, B1, C0, C1, H0, H1;
        const unsigned off = j * 16;
        lds_v2u64(a0 + off, A0, A1);   // y0[4j..4j+3] as two packed pairs
        lds_v2u64(a1 + off, B0, B1);
        lds_v2u64(a2 + off, C0, C1);
        lds_v2u64(ah + off, H0, H1);

        #pragma unroll
        for (int q = 0; q < QPT; q++) {
            u64 t0 = fma2(xp2[q], C0, H0);
            u64 t1 = fma2(xp2[q], C1, H1);
            t0 = fma2(xp1[q], B0, t0);
            t1 = fma2(xp1[q], B1, t1);
            t0 = fma2(xp0[q], A0, t0);
            t1 = fma2(xp0[q], A1, t1);
            float l0, h0, l1, h1;
            unpack2(t0, l0, h0);
            unpack2(t1, l1, h1);
            m0[q] = fmaxf(m0[q], l0);
            m1[q] = fmaxf(m1[q], h0);
            m0[q] = fmaxf(m0[q], l1);
            m1[q] = fmaxf(m1[q], h1);
        }
    }

    // ---- epilogue: t_full = max - hx <= 0, merge via raw-bit umin ----
    const int key0 = (dir * NBATCH + b) * NPTS + qbase + tid;
    #pragma unroll
    for (int q = 0; q < QPT; q++) {
        float tf = fmaxf(m0[q], m1[q]) - hx[q];
        atomicMin(&g_key[key0 + q * THREADS], __float_as_uint(tf));
    }

    // ---- last block performs the final sum (fused reduce) ----
    __threadfence();
    if (tid == 0)
        s_flag = (atomicAdd(&g_count, 1u) == (unsigned)(NBLOCKS - 1)) ? 1u : 0u;
    __syncthreads();
    if (s_flag) {
        const uint4* kp = (const uint4*)g_key;
        float sa = 0.0f, sb = 0.0f, sc = 0.0f, sd = 0.0f;
        for (int i = tid; i < NKEYS / 4; i += THREADS) {
            uint4 v = __ldcg(&kp[i]);
            sa += __uint_as_float(v.x);
            sb += __uint_as_float(v.y);
            sc += __uint_as_float(v.z);
            sd += __uint_as_float(v.w);
        }
        float s = (sa + sb) + (sc + sd);
        #pragma unroll
        for (int off = 16; off > 0; off >>= 1)
            s += __shfl_xor_sync(0xffffffffu, s, off);
        if ((tid & 31) == 0) wsum[tid >> 5] = s;
        __syncthreads();
        if (tid == 0) {
            float t = 0.0f;
            #pragma unroll
            for (int i = 0; i < THREADS / 32; i++) t += wsum[i];
            // min dist per query = -2 * t_full; two means each over B*NPTS
            out[0] = t * (-2.0f / (float)(NBATCH * NPTS));
        }
    }
}

extern "C" void kernel_launch(void* const* d_in, const int* in_sizes, int n_in,
                              void* d_out, int out_size) {
    const float* pred = (const float*)d_in[0];
    const float* targ = (const float*)d_in[1];
    float* out = (float*)d_out;

    chamfer_init_kernel<<<NKEYS / 1024, 1024>>>();
    chamfer_main_kernel<<<NBLOCKS, THREADS>>>(pred, targ, out);
}

// round 8
// speedup vs baseline: 1.2748x; 1.0004x over previous
#include <cuda_runtime.h>
#include <cuda_bf16.h>

// ChamferDistance: B=4, C=3, N=M=8192, fp32 -> scalar.
// Single-direction packed engine:
//   t = x.y - 0.5||y||^2 per (query,target); per-query max(t); min dist = 2hx - 2max.
//   t_full = max(t) - hx <= 0 -> raw-bit atomicMin merge (umin == fmax for t<=0).
// R8: QPT 8 -> 4 to cut regs (~80 -> ~60) and double occupancy (3 -> 4 CTAs/SM,
//     8 warps/SMSP) — R7 profile showed issue=49% with no pipe saturated and
//     5.5 warps/SMSP stalling 11 cyc/inst: latency-hiding, not slots, is the binder.

#define NPTS    8192
#define NBATCH  4
#define THREADS 256
#define QPT     4
#define QTILE   (THREADS * QPT)          // 1024 queries per block
#define NQT     (NPTS / QTILE)           // 8
#define TCHUNK  128                      // targets per block
#define NTC     (NPTS / TCHUNK)          // 64
#define NBLOCKS (2 * NBATCH * NQT * NTC) // 4096
#define NKEYS   (2 * NBATCH * NPTS)      // 65536
#define NEG_INF (-3.402823466e38f)

__device__ unsigned g_key[NKEYS];   // raw bits of t_full (<=0), merged via umin
__device__ unsigned g_count;

typedef unsigned long long u64;

__device__ __forceinline__ u64 fma2(u64 a, u64 b, u64 c) {
    u64 d;
    asm("fma.rn.f32x2 %0, %1, %2, %3;" : "=l"(d) : "l"(a), "l"(b), "l"(c));
    return d;
}
__device__ __forceinline__ u64 pack2(float x) {
    u64 d;
    asm("mov.b64 %0, {%1, %1};" : "=l"(d) : "f"(x));
    return d;
}
__device__ __forceinline__ void unpack2(u64 v, float& lo, float& hi) {
    asm("mov.b64 {%0, %1}, %2;" : "=f"(lo), "=f"(hi) : "l"(v));
}
__device__ __forceinline__ void lds_v2u64(unsigned addr, u64& a, u64& b) {
    asm volatile("ld.shared.v2.u64 {%0, %1}, [%2];" : "=l"(a), "=l"(b) : "r"(addr));
}

__global__ void chamfer_init_kernel() {
    int i = blockIdx.x * blockDim.x + threadIdx.x;
    g_key[i] = 0xFFFFFFFFu;   // umin identity
    if (i == 0) g_count = 0u;
}

__global__ __launch_bounds__(THREADS)
void chamfer_main_kernel(const float* __restrict__ pred,
                         const float* __restrict__ targ,
                         float* __restrict__ out) {
    const int u   = blockIdx.x;
    const int tc  = u & (NTC - 1);
    const int qt  = (u >> 6) & (NQT - 1);
    const int b   = (u >> 9) & (NBATCH - 1);
    const int dir = u >> 11;

    const float* __restrict__ X = (dir ? targ : pred) + (size_t)b * 3 * NPTS;  // queries
    const float* __restrict__ Y = (dir ? pred : targ) + (size_t)b * 3 * NPTS;  // targets

    __shared__ float s_y0[TCHUNK], s_y1[TCHUNK], s_y2[TCHUNK], s_nh[TCHUNK];
    __shared__ float wsum[THREADS / 32];
    __shared__ unsigned s_flag;

    const int tid = threadIdx.x;

    // ---- stage target chunk SoA: y0, y1, y2, nh = -0.5*||y||^2 ----
    const int tbase = tc * TCHUNK;
    if (tid < TCHUNK) {
        float y0 = Y[tbase + tid];
        float y1 = Y[NPTS + tbase + tid];
        float y2 = Y[2 * NPTS + tbase + tid];
        s_y0[tid] = y0;
        s_y1[tid] = y1;
        s_y2[tid] = y2;
        s_nh[tid] = -0.5f * (y0 * y0 + y1 * y1 + y2 * y2);
    }

    // ---- QPT queries per thread: packed broadcast registers ----
    const int qbase = qt * QTILE;
    u64 xp0[QPT], xp1[QPT], xp2[QPT];
    float hx[QPT];
    #pragma unroll
    for (int q = 0; q < QPT; q++) {
        int n = qbase + q * THREADS + tid;
        float x0 = X[n];
        float x1 = X[NPTS + n];
        float x2 = X[2 * NPTS + n];
        xp0[q] = pack2(x0);
        xp1[q] = pack2(x1);
        xp2[q] = pack2(x2);
        hx[q] = 0.5f * (x0 * x0 + x1 * x1 + x2 * x2);
    }
    __syncthreads();

    const unsigned a0 = (unsigned)__cvta_generic_to_shared(s_y0);
    const unsigned a1 = (unsigned)__cvta_generic_to_shared(s_y1);
    const unsigned a2 = (unsigned)__cvta_generic_to_shared(s_y2);
    const unsigned ah = (unsigned)__cvta_generic_to_shared(s_nh);

    float m0[QPT], m1[QPT];
    #pragma unroll
    for (int q = 0; q < QPT; q++) { m0[q] = NEG_INF; m1[q] = NEG_INF; }

    // ---- main loop: 4 targets/iter (broadcast), 4 queries/thread = 16 evals ----
    #pragma unroll 2
    for (int j = 0; j < TCHUNK / 4; j++) {
        u64 A0, A1, B0, B1, C0, C1, H0, H1;
        const unsigned off = j * 16;
        lds_v2u64(a0 + off, A0, A1);   // y0[4j..4j+3] as two packed pairs
        lds_v2u64(a1 + off, B0, B1);
        lds_v2u64(a2 + off, C0, C1);
        lds_v2u64(ah + off, H0, H1);

        #pragma unroll
        for (int q = 0; q < QPT; q++) {
            u64 t0 = fma2(xp2[q], C0, H0);
            u64 t1 = fma2(xp2[q], C1, H1);
            t0 = fma2(xp1[q], B0, t0);
            t1 = fma2(xp1[q], B1, t1);
            t0 = fma2(xp0[q], A0, t0);
            t1 = fma2(xp0[q], A1, t1);
            float l0, h0, l1, h1;
            unpack2(t0, l0, h0);
            unpack2(t1, l1, h1);
            m0[q] = fmaxf(m0[q], l0);
            m1[q] = fmaxf(m1[q], h0);
            m0[q] = fmaxf(m0[q], l1);
            m1[q] = fmaxf(m1[q], h1);
        }
    }

    // ---- epilogue: t_full = max - hx <= 0, merge via raw-bit umin ----
    const int key0 = (dir * NBATCH + b) * NPTS + qbase + tid;
    #pragma unroll
    for (int q = 0; q < QPT; q++) {
        float tf = fmaxf(m0[q], m1[q]) - hx[q];
        atomicMin(&g_key[key0 + q * THREADS], __float_as_uint(tf));
    }

    // ---- last block performs the final sum (fused reduce) ----
    __threadfence();
    if (tid == 0)
        s_flag = (atomicAdd(&g_count, 1u) == (unsigned)(NBLOCKS - 1)) ? 1u : 0u;
    __syncthreads();
    if (s_flag) {
        const uint4* kp = (const uint4*)g_key;
        float sa = 0.0f, sb = 0.0f, sc = 0.0f, sd = 0.0f;
        for (int i = tid; i < NKEYS / 4; i += THREADS) {
            uint4 v = __ldcg(&kp[i]);
            sa += __uint_as_float(v.x);
            sb += __uint_as_float(v.y);
            sc += __uint_as_float(v.z);
            sd += __uint_as_float(v.w);
        }
        float s = (sa + sb) + (sc + sd);
        #pragma unroll
        for (int off = 16; off > 0; off >>= 1)
            s += __shfl_xor_sync(0xffffffffu, s, off);
        if ((tid & 31) == 0) wsum[tid >> 5] = s;
        __syncthreads();
        if (tid == 0) {
            float t = 0.0f;
            #pragma unroll
            for (int i = 0; i < THREADS / 32; i++) t += wsum[i];
            // min dist per query = -2 * t_full; two means each over B*NPTS
            out[0] = t * (-2.0f / (float)(NBATCH * NPTS));
        }
    }
}

extern "C" void kernel_launch(void* const* d_in, const int* in_sizes, int n_in,
                              void* d_out, int out_size) {
    const float* pred = (const float*)d_in[0];
    const float* targ = (const float*)d_in[1];
    float* out = (float*)d_out;

    chamfer_init_kernel<<<NKEYS / 1024, 1024>>>();
    chamfer_main_kernel<<<NBLOCKS, THREADS>>>(pred, targ, out);
}